// round 1
// baseline (speedup 1.0000x reference)
#include <cuda_runtime.h>
#include <math.h>

#define D_MODEL 1024
#define HEADS   16
#define HDIM    64
#define BATCH   4
#define SEQ     1024
#define SCALE   0.03125f   // 1/sqrt(1024)

#define PAD     68          // 64 + 4 floats row pitch (keeps float4 alignment)

// Scratch for attention output [B, L, D] (allocation-free: device global)
__device__ float g_attn[BATCH * SEQ * D_MODEL];

// ---------------------------------------------------------------------------
// Fused flash attention: one block = (q-block of 64 rows, head h, batch b)
// smem: Qs_T[d][r] (pre-scaled by 1/32), Ks_T[d][c] (reused as P_T[c][r]),
//       Vs[c][d]. All inner-loop reads are LDS.128.
// ---------------------------------------------------------------------------
__global__ void attn_kernel(const float* __restrict__ Q,
                            const float* __restrict__ K,
                            const float* __restrict__ V) {
    extern __shared__ float sm[];
    float* Qs = sm;                 // [64][PAD]  Qs[d*PAD + r]
    float* Ks = sm + 64 * PAD;      // [64][PAD]  Ks[d*PAD + c]  (later P_T[c*PAD + r])
    float* Vs = sm + 2 * 64 * PAD;  // [64][PAD]  Vs[c*PAD + d]

    const int qb = blockIdx.x;
    const int h  = blockIdx.y;
    const int b  = blockIdx.z;
    const int t  = threadIdx.x;
    const int tx = t & 15;          // 0..15  (column group)
    const int ty = t >> 4;          // 0..15  (row group)
    const int d4 = tx * 4;

    const size_t head_off = (size_t)b * SEQ * D_MODEL + (size_t)h * HDIM;
    const float* Qb = Q + head_off;
    const float* Kb = K + head_off;
    const float* Vb = V + head_off;

    // Load Q tile, transposed + pre-scaled
    #pragma unroll
    for (int it = 0; it < 4; ++it) {
        int r = ty + 16 * it;
        int q = qb * 64 + r;
        float4 v = *(const float4*)(Qb + (size_t)q * D_MODEL + d4);
        Qs[(d4 + 0) * PAD + r] = v.x * SCALE;
        Qs[(d4 + 1) * PAD + r] = v.y * SCALE;
        Qs[(d4 + 2) * PAD + r] = v.z * SCALE;
        Qs[(d4 + 3) * PAD + r] = v.w * SCALE;
    }

    float o[4][4];
    float m_i[4], l_i[4];
    #pragma unroll
    for (int i = 0; i < 4; ++i) {
        m_i[i] = -INFINITY;
        l_i[i] = 0.0f;
        #pragma unroll
        for (int j = 0; j < 4; ++j) o[i][j] = 0.0f;
    }

    for (int kb = 0; kb < SEQ / 64; ++kb) {
        __syncthreads();   // previous iteration's smem reads complete
        // Load K (transposed) and V (natural) tiles
        #pragma unroll
        for (int it = 0; it < 4; ++it) {
            int c  = ty + 16 * it;
            int kv = kb * 64 + c;
            float4 kv4 = *(const float4*)(Kb + (size_t)kv * D_MODEL + d4);
            Ks[(d4 + 0) * PAD + c] = kv4.x;
            Ks[(d4 + 1) * PAD + c] = kv4.y;
            Ks[(d4 + 2) * PAD + c] = kv4.z;
            Ks[(d4 + 3) * PAD + c] = kv4.w;
            float4 vv4 = *(const float4*)(Vb + (size_t)kv * D_MODEL + d4);
            *(float4*)(Vs + c * PAD + d4) = vv4;
        }
        __syncthreads();

        // S = (Q*scale) @ K^T   (4x4 per thread)
        float s[4][4];
        #pragma unroll
        for (int i = 0; i < 4; ++i)
            #pragma unroll
            for (int j = 0; j < 4; ++j) s[i][j] = 0.0f;

        #pragma unroll 8
        for (int d = 0; d < 64; ++d) {
            float4 qv = *(const float4*)(Qs + d * PAD + 4 * ty);
            float4 kv4 = *(const float4*)(Ks + d * PAD + 4 * tx);
            float qa[4] = {qv.x, qv.y, qv.z, qv.w};
            float ka[4] = {kv4.x, kv4.y, kv4.z, kv4.w};
            #pragma unroll
            for (int i = 0; i < 4; ++i)
                #pragma unroll
                for (int j = 0; j < 4; ++j)
                    s[i][j] = fmaf(qa[i], ka[j], s[i][j]);
        }

        // Online softmax update (row reductions across tx within 16-lane groups)
        float p[4][4];
        #pragma unroll
        for (int i = 0; i < 4; ++i) {
            float rm = fmaxf(fmaxf(s[i][0], s[i][1]), fmaxf(s[i][2], s[i][3]));
            #pragma unroll
            for (int off = 1; off < 16; off <<= 1)
                rm = fmaxf(rm, __shfl_xor_sync(0xffffffffu, rm, off, 16));
            float mn = fmaxf(m_i[i], rm);
            float al = __expf(m_i[i] - mn);
            m_i[i] = mn;
            float rs = 0.0f;
            #pragma unroll
            for (int j = 0; j < 4; ++j) {
                p[i][j] = __expf(s[i][j] - mn);
                rs += p[i][j];
            }
            #pragma unroll
            for (int off = 1; off < 16; off <<= 1)
                rs += __shfl_xor_sync(0xffffffffu, rs, off, 16);
            l_i[i] = l_i[i] * al + rs;
            #pragma unroll
            for (int j = 0; j < 4; ++j) o[i][j] *= al;
        }

        __syncthreads();   // everyone done reading Ks as K
        // Store P transposed into Ks buffer: P_T[c][r]
        #pragma unroll
        for (int i = 0; i < 4; ++i)
            #pragma unroll
            for (int j = 0; j < 4; ++j)
                Ks[(4 * tx + j) * PAD + 4 * ty + i] = p[i][j];
        __syncthreads();

        // O += P @ V
        #pragma unroll 8
        for (int c = 0; c < 64; ++c) {
            float4 pv = *(const float4*)(Ks + c * PAD + 4 * ty);
            float4 vv = *(const float4*)(Vs + c * PAD + 4 * tx);
            float pa[4] = {pv.x, pv.y, pv.z, pv.w};
            float va[4] = {vv.x, vv.y, vv.z, vv.w};
            #pragma unroll
            for (int i = 0; i < 4; ++i)
                #pragma unroll
                for (int j = 0; j < 4; ++j)
                    o[i][j] = fmaf(pa[i], va[j], o[i][j]);
        }
    }

    // Normalize and write to scratch
    #pragma unroll
    for (int i = 0; i < 4; ++i) {
        float inv = 1.0f / l_i[i];
        int q = qb * 64 + 4 * ty + i;
        float4 r;
        r.x = o[i][0] * inv; r.y = o[i][1] * inv;
        r.z = o[i][2] * inv; r.w = o[i][3] * inv;
        *(float4*)(g_attn + (size_t)b * SEQ * D_MODEL + (size_t)q * D_MODEL
                   + h * HDIM + 4 * tx) = r;
    }
}

// ---------------------------------------------------------------------------
// Output projection: out[m][n] = sum_k g_attn[m][k] * W[n][k] + bias[n]
// M = B*L = 4096, N = K = 1024.  64x64x64 tiles, 4x4 per thread.
// ---------------------------------------------------------------------------
__global__ void proj_kernel(const float* __restrict__ W,
                            const float* __restrict__ bias,
                            float* __restrict__ out) {
    __shared__ float As[64 * PAD];   // As[k][m]
    __shared__ float Ws[64 * PAD];   // Ws[k][n]

    const int nb = blockIdx.x;
    const int mb = blockIdx.y;
    const int t  = threadIdx.x;
    const int tx = t & 15;
    const int ty = t >> 4;
    const int k4 = tx * 4;

    float acc[4][4];
    #pragma unroll
    for (int i = 0; i < 4; ++i)
        #pragma unroll
        for (int j = 0; j < 4; ++j) acc[i][j] = 0.0f;

    for (int kb = 0; kb < D_MODEL / 64; ++kb) {
        __syncthreads();
        #pragma unroll
        for (int it = 0; it < 4; ++it) {
            int r = ty + 16 * it;
            float4 a = *(const float4*)(g_attn + (size_t)(mb * 64 + r) * D_MODEL
                                        + kb * 64 + k4);
            As[(k4 + 0) * PAD + r] = a.x;
            As[(k4 + 1) * PAD + r] = a.y;
            As[(k4 + 2) * PAD + r] = a.z;
            As[(k4 + 3) * PAD + r] = a.w;
            float4 w = *(const float4*)(W + (size_t)(nb * 64 + r) * D_MODEL
                                        + kb * 64 + k4);
            Ws[(k4 + 0) * PAD + r] = w.x;
            Ws[(k4 + 1) * PAD + r] = w.y;
            Ws[(k4 + 2) * PAD + r] = w.z;
            Ws[(k4 + 3) * PAD + r] = w.w;
        }
        __syncthreads();

        #pragma unroll 8
        for (int k = 0; k < 64; ++k) {
            float4 av = *(const float4*)(As + k * PAD + 4 * ty);
            float4 wv = *(const float4*)(Ws + k * PAD + 4 * tx);
            float aa[4] = {av.x, av.y, av.z, av.w};
            float wa[4] = {wv.x, wv.y, wv.z, wv.w};
            #pragma unroll
            for (int i = 0; i < 4; ++i)
                #pragma unroll
                for (int j = 0; j < 4; ++j)
                    acc[i][j] = fmaf(aa[i], wa[j], acc[i][j]);
        }
    }

    float4 bv = *(const float4*)(bias + nb * 64 + 4 * tx);
    float ba[4] = {bv.x, bv.y, bv.z, bv.w};
    #pragma unroll
    for (int i = 0; i < 4; ++i) {
        int mrow = mb * 64 + 4 * ty + i;
        float4 r;
        r.x = acc[i][0] + ba[0];
        r.y = acc[i][1] + ba[1];
        r.z = acc[i][2] + ba[2];
        r.w = acc[i][3] + ba[3];
        *(float4*)(out + (size_t)mrow * D_MODEL + nb * 64 + 4 * tx) = r;
    }
}

extern "C" void kernel_launch(void* const* d_in, const int* in_sizes, int n_in,
                              void* d_out, int out_size) {
    const float* Q   = (const float*)d_in[0];
    const float* K   = (const float*)d_in[1];
    const float* V   = (const float*)d_in[2];
    const float* W_H = (const float*)d_in[3];
    const float* b_H = (const float*)d_in[4];
    (void)in_sizes; (void)n_in; (void)out_size;

    const int attn_smem = 3 * 64 * PAD * sizeof(float);   // 52224 B > 48KB default
    cudaFuncSetAttribute(attn_kernel,
                         cudaFuncAttributeMaxDynamicSharedMemorySize, attn_smem);

    dim3 agrid(SEQ / 64, HEADS, BATCH);
    attn_kernel<<<agrid, 256, attn_smem>>>(Q, K, V);

    dim3 pgrid(D_MODEL / 64, (BATCH * SEQ) / 64);
    proj_kernel<<<pgrid, 256>>>(W_H, b_H, (float*)d_out);
}

// round 3
// speedup vs baseline: 1.8853x; 1.8853x over previous
#include <cuda_runtime.h>
#include <math.h>
#include <cstdint>

#define D_MODEL 1024
#define HEADS   16
#define HDIM    64
#define BATCH   4
#define SEQ     1024
#define SCALE   0.03125f   // 1/sqrt(1024)

// Scratch for attention output [B, L, D]
__device__ float g_attn[BATCH * SEQ * D_MODEL];

// ---------------------------------------------------------------------------
// tf32 helpers (plain sm_103-compatible: mma.sync is sm_80-era, no 'a' gate)
// ---------------------------------------------------------------------------
__device__ __forceinline__ float tf32r(float x) {
    uint32_t u;
    asm("cvt.rna.tf32.f32 %0, %1;" : "=r"(u) : "f"(x));
    return __uint_as_float(u);
}

// D(16x8) += A(16x8) * B(8x8), tf32 inputs, f32 accumulate.
// A row-major fragment: a0=(g,t) a1=(g+8,t) a2=(g,t+4) a3=(g+8,t+4)
// B col-major fragment: b0=(k=t, n=g) b1=(k=t+4, n=g)     [g=lane>>2, t=lane&3]
// C: c0=(g,2t) c1=(g,2t+1) c2=(g+8,2t) c3=(g+8,2t+1)
__device__ __forceinline__ void mma8(float c[4],
                                     uint32_t a0, uint32_t a1, uint32_t a2, uint32_t a3,
                                     uint32_t b0, uint32_t b1) {
    asm volatile(
        "mma.sync.aligned.m16n8k8.row.col.f32.tf32.tf32.f32 "
        "{%0,%1,%2,%3}, {%4,%5,%6,%7}, {%8,%9}, {%0,%1,%2,%3};"
        : "+f"(c[0]), "+f"(c[1]), "+f"(c[2]), "+f"(c[3])
        : "r"(a0), "r"(a1), "r"(a2), "r"(a3), "r"(b0), "r"(b1));
}

#define FB(x) __float_as_uint(x)

// SMEM pitches (floats). A-role arrays: 68 (banks 4*row+col -> distinct).
// B-role arrays: 72 (banks 8*k+n -> distinct).
#define QP 68
#define KP 72
#define VP 72
#define PP 68

// ===========================================================================
// Flash attention, tf32 mma.sync.  Block = (q-block 64, head, batch), 128 thr.
// Each warp owns 16 q-rows x 64 cols.
// ===========================================================================
__global__ void __launch_bounds__(128)
attn_kernel(const float* __restrict__ Q,
            const float* __restrict__ K,
            const float* __restrict__ V) {
    extern __shared__ float sm[];
    float* Qs = sm;               // [64][QP]  row-major (m x k), pre-scaled tf32
    float* Ks = Qs + 64 * QP;     // [64][KP]  d-major:  Ks[d][kv]  (B layout)
    float* Vs = Ks + 64 * KP;     // [64][VP]  kv-major: Vs[kv][d]  (B layout)
    float* Ps = Vs + 64 * VP;     // [64][PP]  row-major (q x kv)   (A layout)

    const int qb = blockIdx.x, h = blockIdx.y, b = blockIdx.z;
    const int tid  = threadIdx.x;
    const int lane = tid & 31, warp = tid >> 5;
    const int gid  = lane >> 2, tig = lane & 3;
    const int wm   = warp * 16;

    const size_t base = (size_t)b * SEQ * D_MODEL + (size_t)h * HDIM;
    const float* Qb = Q + base;
    const float* Kb = K + base;
    const float* Vb = V + base;

    // ---- Q tile: 64x64, scaled + tf32-rounded, row-major ----
    #pragma unroll
    for (int p = 0; p < 8; ++p) {
        int idx = tid + p * 128;
        int row = idx >> 4, c4 = idx & 15;
        float4 v = *(const float4*)(Qb + (size_t)(qb * 64 + row) * D_MODEL + c4 * 4);
        float4 t;
        t.x = tf32r(v.x * SCALE); t.y = tf32r(v.y * SCALE);
        t.z = tf32r(v.z * SCALE); t.w = tf32r(v.w * SCALE);
        *(float4*)(Qs + row * QP + c4 * 4) = t;
    }

    float of[8][4];
    #pragma unroll
    for (int j = 0; j < 8; ++j)
        #pragma unroll
        for (int i = 0; i < 4; ++i) of[j][i] = 0.0f;
    float m0 = -INFINITY, m1 = -INFINITY, l0 = 0.0f, l1 = 0.0f;

    for (int kb = 0; kb < SEQ / 64; ++kb) {
        __syncthreads();   // previous iter's Ks/Vs reads complete
        // ---- K (transposed to [d][kv]) and V ([kv][d]) tiles ----
        #pragma unroll
        for (int p = 0; p < 8; ++p) {
            int idx = tid + p * 128;
            int r = idx >> 4, c4 = idx & 15;
            int kv = kb * 64 + r;
            float4 kvec = *(const float4*)(Kb + (size_t)kv * D_MODEL + c4 * 4);
            Ks[(c4 * 4 + 0) * KP + r] = tf32r(kvec.x);
            Ks[(c4 * 4 + 1) * KP + r] = tf32r(kvec.y);
            Ks[(c4 * 4 + 2) * KP + r] = tf32r(kvec.z);
            Ks[(c4 * 4 + 3) * KP + r] = tf32r(kvec.w);
            float4 vvec = *(const float4*)(Vb + (size_t)kv * D_MODEL + c4 * 4);
            float4 tv;
            tv.x = tf32r(vvec.x); tv.y = tf32r(vvec.y);
            tv.z = tf32r(vvec.z); tv.w = tf32r(vvec.w);
            *(float4*)(Vs + r * VP + c4 * 4) = tv;
        }
        __syncthreads();

        // ---- S = Qs @ Ks  (16x64 per warp) ----
        float sf[8][4];
        #pragma unroll
        for (int j = 0; j < 8; ++j)
            #pragma unroll
            for (int i = 0; i < 4; ++i) sf[j][i] = 0.0f;

        #pragma unroll
        for (int k0 = 0; k0 < 64; k0 += 8) {
            uint32_t a0 = FB(Qs[(wm + gid    ) * QP + k0 + tig    ]);
            uint32_t a1 = FB(Qs[(wm + gid + 8) * QP + k0 + tig    ]);
            uint32_t a2 = FB(Qs[(wm + gid    ) * QP + k0 + tig + 4]);
            uint32_t a3 = FB(Qs[(wm + gid + 8) * QP + k0 + tig + 4]);
            #pragma unroll
            for (int j = 0; j < 8; ++j) {
                uint32_t b0 = FB(Ks[(k0 + tig    ) * KP + j * 8 + gid]);
                uint32_t b1 = FB(Ks[(k0 + tig + 4) * KP + j * 8 + gid]);
                mma8(sf[j], a0, a1, a2, a3, b0, b1);
            }
        }

        // ---- online softmax on C fragments ----
        float rm0 = -INFINITY, rm1 = -INFINITY;
        #pragma unroll
        for (int j = 0; j < 8; ++j) {
            rm0 = fmaxf(rm0, fmaxf(sf[j][0], sf[j][1]));
            rm1 = fmaxf(rm1, fmaxf(sf[j][2], sf[j][3]));
        }
        rm0 = fmaxf(rm0, __shfl_xor_sync(0xffffffffu, rm0, 1));
        rm0 = fmaxf(rm0, __shfl_xor_sync(0xffffffffu, rm0, 2));
        rm1 = fmaxf(rm1, __shfl_xor_sync(0xffffffffu, rm1, 1));
        rm1 = fmaxf(rm1, __shfl_xor_sync(0xffffffffu, rm1, 2));

        float mn0 = fmaxf(m0, rm0), mn1 = fmaxf(m1, rm1);
        float al0 = __expf(m0 - mn0), al1 = __expf(m1 - mn1);
        m0 = mn0; m1 = mn1;

        float rs0 = 0.0f, rs1 = 0.0f;
        #pragma unroll
        for (int j = 0; j < 8; ++j) {
            sf[j][0] = __expf(sf[j][0] - mn0);
            sf[j][1] = __expf(sf[j][1] - mn0);
            sf[j][2] = __expf(sf[j][2] - mn1);
            sf[j][3] = __expf(sf[j][3] - mn1);
            rs0 += sf[j][0] + sf[j][1];
            rs1 += sf[j][2] + sf[j][3];
        }
        rs0 += __shfl_xor_sync(0xffffffffu, rs0, 1);
        rs0 += __shfl_xor_sync(0xffffffffu, rs0, 2);
        rs1 += __shfl_xor_sync(0xffffffffu, rs1, 1);
        rs1 += __shfl_xor_sync(0xffffffffu, rs1, 2);
        l0 = l0 * al0 + rs0;
        l1 = l1 * al1 + rs1;

        #pragma unroll
        for (int j = 0; j < 8; ++j) {
            of[j][0] *= al0; of[j][1] *= al0;
            of[j][2] *= al1; of[j][3] *= al1;
        }

        // ---- P -> smem (warp-private rows), A layout ----
        #pragma unroll
        for (int j = 0; j < 8; ++j) {
            int c = j * 8 + 2 * tig;
            Ps[(wm + gid    ) * PP + c    ] = tf32r(sf[j][0]);
            Ps[(wm + gid    ) * PP + c + 1] = tf32r(sf[j][1]);
            Ps[(wm + gid + 8) * PP + c    ] = tf32r(sf[j][2]);
            Ps[(wm + gid + 8) * PP + c + 1] = tf32r(sf[j][3]);
        }
        __syncwarp();

        // ---- O += P @ V ----
        #pragma unroll
        for (int k0 = 0; k0 < 64; k0 += 8) {
            uint32_t a0 = FB(Ps[(wm + gid    ) * PP + k0 + tig    ]);
            uint32_t a1 = FB(Ps[(wm + gid + 8) * PP + k0 + tig    ]);
            uint32_t a2 = FB(Ps[(wm + gid    ) * PP + k0 + tig + 4]);
            uint32_t a3 = FB(Ps[(wm + gid + 8) * PP + k0 + tig + 4]);
            #pragma unroll
            for (int j = 0; j < 8; ++j) {
                uint32_t b0 = FB(Vs[(k0 + tig    ) * VP + j * 8 + gid]);
                uint32_t b1 = FB(Vs[(k0 + tig + 4) * VP + j * 8 + gid]);
                mma8(of[j], a0, a1, a2, a3, b0, b1);
            }
        }
    }

    // ---- epilogue: normalize, write scratch ----
    float inv0 = 1.0f / l0, inv1 = 1.0f / l1;
    int q0 = qb * 64 + wm + gid;
    float* o0 = g_attn + (size_t)b * SEQ * D_MODEL + (size_t)q0 * D_MODEL + h * HDIM;
    float* o1 = o0 + 8 * D_MODEL;
    #pragma unroll
    for (int j = 0; j < 8; ++j) {
        int c = j * 8 + 2 * tig;
        float2 r0 = make_float2(of[j][0] * inv0, of[j][1] * inv0);
        float2 r1 = make_float2(of[j][2] * inv1, of[j][3] * inv1);
        *(float2*)(o0 + c) = r0;
        *(float2*)(o1 + c) = r1;
    }
}

// ===========================================================================
// Projection: out[m][n] = sum_k g_attn[m][k] * W[n][k] + bias[n]
// tf32 mma.sync, 64x64 block tile, 4 warps (16x64 each), K-chunks of 64.
// ===========================================================================
#define AJP 68
#define WJP 72

__global__ void __launch_bounds__(128)
proj_kernel(const float* __restrict__ W,
            const float* __restrict__ bias,
            float* __restrict__ out) {
    __shared__ float As[64 * AJP];   // [m][k]  A layout
    __shared__ float Ws[64 * WJP];   // [k][n]  B layout

    const int nb = blockIdx.x, mb = blockIdx.y;
    const int tid  = threadIdx.x;
    const int lane = tid & 31, warp = tid >> 5;
    const int gid  = lane >> 2, tig = lane & 3;
    const int wm   = warp * 16;

    float acc[8][4];
    #pragma unroll
    for (int j = 0; j < 8; ++j)
        #pragma unroll
        for (int i = 0; i < 4; ++i) acc[j][i] = 0.0f;

    for (int kb = 0; kb < D_MODEL / 64; ++kb) {
        __syncthreads();
        #pragma unroll
        for (int p = 0; p < 8; ++p) {
            int idx = tid + p * 128;
            int r = idx >> 4, c4 = idx & 15;
            float4 a = *(const float4*)(g_attn + (size_t)(mb * 64 + r) * D_MODEL
                                        + kb * 64 + c4 * 4);
            float4 ta;
            ta.x = tf32r(a.x); ta.y = tf32r(a.y);
            ta.z = tf32r(a.z); ta.w = tf32r(a.w);
            *(float4*)(As + r * AJP + c4 * 4) = ta;
            float4 w = *(const float4*)(W + (size_t)(nb * 64 + r) * D_MODEL
                                        + kb * 64 + c4 * 4);
            Ws[(c4 * 4 + 0) * WJP + r] = tf32r(w.x);
            Ws[(c4 * 4 + 1) * WJP + r] = tf32r(w.y);
            Ws[(c4 * 4 + 2) * WJP + r] = tf32r(w.z);
            Ws[(c4 * 4 + 3) * WJP + r] = tf32r(w.w);
        }
        __syncthreads();

        #pragma unroll
        for (int k0 = 0; k0 < 64; k0 += 8) {
            uint32_t a0 = FB(As[(wm + gid    ) * AJP + k0 + tig    ]);
            uint32_t a1 = FB(As[(wm + gid + 8) * AJP + k0 + tig    ]);
            uint32_t a2 = FB(As[(wm + gid    ) * AJP + k0 + tig + 4]);
            uint32_t a3 = FB(As[(wm + gid + 8) * AJP + k0 + tig + 4]);
            #pragma unroll
            for (int j = 0; j < 8; ++j) {
                uint32_t b0 = FB(Ws[(k0 + tig    ) * WJP + j * 8 + gid]);
                uint32_t b1 = FB(Ws[(k0 + tig + 4) * WJP + j * 8 + gid]);
                mma8(acc[j], a0, a1, a2, a3, b0, b1);
            }
        }
    }

    int m0 = mb * 64 + wm + gid;
    float* r0 = out + (size_t)m0 * D_MODEL + nb * 64;
    float* r1 = r0 + 8 * D_MODEL;
    #pragma unroll
    for (int j = 0; j < 8; ++j) {
        int c = j * 8 + 2 * tig;
        float bv0 = bias[nb * 64 + c], bv1 = bias[nb * 64 + c + 1];
        *(float2*)(r0 + c) = make_float2(acc[j][0] + bv0, acc[j][1] + bv1);
        *(float2*)(r1 + c) = make_float2(acc[j][2] + bv0, acc[j][3] + bv1);
    }
}

// ===========================================================================
extern "C" void kernel_launch(void* const* d_in, const int* in_sizes, int n_in,
                              void* d_out, int out_size) {
    const float* Q   = (const float*)d_in[0];
    const float* K   = (const float*)d_in[1];
    const float* V   = (const float*)d_in[2];
    const float* W_H = (const float*)d_in[3];
    const float* b_H = (const float*)d_in[4];
    (void)in_sizes; (void)n_in; (void)out_size;

    const int attn_smem = (64 * QP + 64 * KP + 64 * VP + 64 * PP) * sizeof(float);
    cudaFuncSetAttribute(attn_kernel,
                         cudaFuncAttributeMaxDynamicSharedMemorySize, attn_smem);
    dim3 agrid(SEQ / 64, HEADS, BATCH);
    attn_kernel<<<agrid, 128, attn_smem>>>(Q, K, V);

    dim3 pgrid(D_MODEL / 64, (BATCH * SEQ) / 64);
    proj_kernel<<<pgrid, 128>>>(W_H, b_H, (float*)d_out);
}

// round 5
// speedup vs baseline: 2.5292x; 1.3415x over previous
#include <cuda_runtime.h>
#include <math.h>
#include <cstdint>

#define D_MODEL 1024
#define HEADS   16
#define HDIM    64
#define BATCH   4
#define SEQ     1024
#define SCALE   0.03125f   // 1/sqrt(1024)

// Scratch for attention output [B, L, D]
__device__ float g_attn[BATCH * SEQ * D_MODEL];

// ---------------------------------------------------------------------------
// tf32 mma.sync helpers (sm_80-era PTX, passes the compute_103 target)
// ---------------------------------------------------------------------------
__device__ __forceinline__ float tf32r(float x) {
    uint32_t u;
    asm("cvt.rna.tf32.f32 %0, %1;" : "=r"(u) : "f"(x));
    return __uint_as_float(u);
}
// A frag: a0=(g,t) a1=(g+8,t) a2=(g,t+4) a3=(g+8,t+4);  g=lane>>2, t=lane&3
// B frag: b0=(k=t,n=g) b1=(k=t+4,n=g)
// C frag: c0=(g,2t) c1=(g,2t+1) c2=(g+8,2t) c3=(g+8,2t+1)
__device__ __forceinline__ void mma8(float c[4], const float4& a,
                                     uint32_t b0, uint32_t b1) {
    asm volatile(
        "mma.sync.aligned.m16n8k8.row.col.f32.tf32.tf32.f32 "
        "{%0,%1,%2,%3}, {%4,%5,%6,%7}, {%8,%9}, {%0,%1,%2,%3};"
        : "+f"(c[0]), "+f"(c[1]), "+f"(c[2]), "+f"(c[3])
        : "r"(__float_as_uint(a.x)), "r"(__float_as_uint(a.y)),
          "r"(__float_as_uint(a.z)), "r"(__float_as_uint(a.w)),
          "r"(b0), "r"(b1));
}

// Packed layouts (float indices):
//  A-pack: ((kg*NMB + mblk)*32 + lane)*4 + slot,  slot = hi_m + 2*hi_k
//  B-pack: ((kg*NNB + nblk)*32 + lane)*2 + p,     p = hi_k
__device__ __forceinline__ int paA(int kg, int mblk, int lane, int NMB) {
    return ((kg * NMB + mblk) * 32 + lane) * 4;
}
__device__ __forceinline__ int paB(int kg, int nblk, int lane, int NNB) {
    return ((kg * NNB + nblk) * 32 + lane) * 2;
}

// ===========================================================================
// Flash attention.  Block = (q-tile 128, head, batch), 256 threads, 8 warps.
// Warp w owns q rows w*16..w*16+15 over the full 64-wide kv tile.
// ===========================================================================
#define AT_QF (8 * 8 * 128)   // Q packed-A: kg8 x mblk8 x 128
#define AT_KF (8 * 8 * 64)    // K packed-B: kg8 x nblk8 x 64
#define AT_VF (8 * 8 * 64)    // V packed-B
#define AT_PF (8 * 8 * 128)   // P packed-A

__global__ void __launch_bounds__(256)
attn_kernel(const float* __restrict__ Q,
            const float* __restrict__ K,
            const float* __restrict__ V) {
    extern __shared__ float sm[];
    float* Qs = sm;
    float* Ks = Qs + AT_QF;
    float* Vs = Ks + AT_KF;
    float* Ps = Vs + AT_VF;

    const int qb = blockIdx.x, h = blockIdx.y, b = blockIdx.z;
    const int tid  = threadIdx.x;
    const int lane = tid & 31, warp = tid >> 5;
    const int g    = lane >> 2, t = lane & 3;

    const size_t base = (size_t)b * SEQ * D_MODEL + (size_t)h * HDIM;
    const float* Qb = Q + base;
    const float* Kb = K + base;
    const float* Vb = V + base;

    // ---- fill Q packed-A (scaled, tf32) ----
    #pragma unroll
    for (int p8 = 0; p8 < 8; ++p8) {
        int i = tid + p8 * 256;          // 0..2047 float4s
        int m = i >> 4, kq = i & 15;     // row, quad-col (d = kq*4+e)
        float4 v = *(const float4*)(Qb + (size_t)(qb * 128 + m) * D_MODEL + kq * 4);
        float va[4] = {tf32r(v.x * SCALE), tf32r(v.y * SCALE),
                       tf32r(v.z * SCALE), tf32r(v.w * SCALE)};
        int mblk = m >> 4, r = m & 15, him = r >> 3, gg = r & 7;
        int kg = kq >> 1, hik = kq & 1, slot = him + 2 * hik;
        #pragma unroll
        for (int s = 0; s < 4; ++s) {
            int e = (s + gg + kg) & 3;
            Qs[paA(kg, mblk, gg * 4 + e, 8) + slot] = va[e];
        }
    }

    float of[8][4];
    #pragma unroll
    for (int j = 0; j < 8; ++j)
        #pragma unroll
        for (int i = 0; i < 4; ++i) of[j][i] = 0.0f;
    float m0 = -INFINITY, m1 = -INFINITY, l0 = 0.0f, l1 = 0.0f;

    for (int kb = 0; kb < SEQ / 64; ++kb) {
        // ---- fill K packed-B ----
        #pragma unroll
        for (int p4 = 0; p4 < 4; ++p4) {
            int i = tid + p4 * 256;          // 0..1023
            int kvr = i >> 4, kq = i & 15;   // kv row, d quad
            float4 v = *(const float4*)(Kb + (size_t)(kb * 64 + kvr) * D_MODEL + kq * 4);
            float va[4] = {tf32r(v.x), tf32r(v.y), tf32r(v.z), tf32r(v.w)};
            int nblk = kvr >> 3, gg = kvr & 7;
            int kg = kq >> 1, p = kq & 1;
            #pragma unroll
            for (int s = 0; s < 4; ++s) {
                int e = (s + kg) & 3;
                Ks[paB(kg, nblk, gg * 4 + e, 8) + p] = va[e];
            }
        }
        // ---- fill V packed-B (k-role = kv, n-role = d) ----
        #pragma unroll
        for (int p4 = 0; p4 < 4; ++p4) {
            int idx = tid + p4 * 256;        // 0..1023
            int kvr = idx & 63, dq = idx >> 6;
            float4 v = *(const float4*)(Vb + (size_t)(kb * 64 + kvr) * D_MODEL + dq * 4);
            float va[4] = {tf32r(v.x), tf32r(v.y), tf32r(v.z), tf32r(v.w)};
            int kg = kvr >> 3, tt = kvr & 3, p = ((kvr & 7) >= 4) ? 1 : 0;
            #pragma unroll
            for (int s = 0; s < 4; ++s) {
                int e = (s + kg) & 3;
                int n = dq * 4 + e;
                Vs[paB(kg, n >> 3, (n & 7) * 4 + tt, 8) + p] = va[e];
            }
        }
        __syncthreads();   // K/V tiles ready (and Qs on first iter)

        // ---- S = Q @ K^T : warp tile 16x64 ----
        float sf[8][4];
        #pragma unroll
        for (int j = 0; j < 8; ++j)
            #pragma unroll
            for (int i = 0; i < 4; ++i) sf[j][i] = 0.0f;

        #pragma unroll
        for (int kg = 0; kg < 8; ++kg) {
            float4 a = *(const float4*)(Qs + paA(kg, warp, lane, 8));
            #pragma unroll
            for (int j = 0; j < 8; ++j) {
                float2 bv = *(const float2*)(Ks + paB(kg, j, lane, 8));
                mma8(sf[j], a, __float_as_uint(bv.x), __float_as_uint(bv.y));
            }
        }

        // ---- online softmax ----
        float rm0 = -INFINITY, rm1 = -INFINITY;
        #pragma unroll
        for (int j = 0; j < 8; ++j) {
            rm0 = fmaxf(rm0, fmaxf(sf[j][0], sf[j][1]));
            rm1 = fmaxf(rm1, fmaxf(sf[j][2], sf[j][3]));
        }
        rm0 = fmaxf(rm0, __shfl_xor_sync(0xffffffffu, rm0, 1));
        rm0 = fmaxf(rm0, __shfl_xor_sync(0xffffffffu, rm0, 2));
        rm1 = fmaxf(rm1, __shfl_xor_sync(0xffffffffu, rm1, 1));
        rm1 = fmaxf(rm1, __shfl_xor_sync(0xffffffffu, rm1, 2));
        float mn0 = fmaxf(m0, rm0), mn1 = fmaxf(m1, rm1);
        float al0 = __expf(m0 - mn0), al1 = __expf(m1 - mn1);
        m0 = mn0; m1 = mn1;
        float rs0 = 0.0f, rs1 = 0.0f;
        #pragma unroll
        for (int j = 0; j < 8; ++j) {
            sf[j][0] = __expf(sf[j][0] - mn0);
            sf[j][1] = __expf(sf[j][1] - mn0);
            sf[j][2] = __expf(sf[j][2] - mn1);
            sf[j][3] = __expf(sf[j][3] - mn1);
            rs0 += sf[j][0] + sf[j][1];
            rs1 += sf[j][2] + sf[j][3];
        }
        rs0 += __shfl_xor_sync(0xffffffffu, rs0, 1);
        rs0 += __shfl_xor_sync(0xffffffffu, rs0, 2);
        rs1 += __shfl_xor_sync(0xffffffffu, rs1, 1);
        rs1 += __shfl_xor_sync(0xffffffffu, rs1, 2);
        l0 = l0 * al0 + rs0;
        l1 = l1 * al1 + rs1;
        #pragma unroll
        for (int j = 0; j < 8; ++j) {
            of[j][0] *= al0; of[j][1] *= al0;
            of[j][2] *= al1; of[j][3] *= al1;
        }

        // ---- P -> packed-A smem (warp-private mblk = warp) ----
        #pragma unroll
        for (int j = 0; j < 8; ++j) {
            int hik = (t >= 2) ? 2 : 0;
            int l0i = g * 4 + ((2 * t) & 3);
            int l1i = g * 4 + ((2 * t + 1) & 3);
            float* Pj = Ps + ((j * 8 + warp) * 32) * 4;
            Pj[l0i * 4 + hik    ] = tf32r(sf[j][0]);
            Pj[l1i * 4 + hik    ] = tf32r(sf[j][1]);
            Pj[l0i * 4 + hik + 1] = tf32r(sf[j][2]);
            Pj[l1i * 4 + hik + 1] = tf32r(sf[j][3]);
        }
        __syncwarp();

        // ---- O += P @ V ----
        #pragma unroll
        for (int kg = 0; kg < 8; ++kg) {
            float4 a = *(const float4*)(Ps + paA(kg, warp, lane, 8));
            #pragma unroll
            for (int j = 0; j < 8; ++j) {
                float2 bv = *(const float2*)(Vs + paB(kg, j, lane, 8));
                mma8(of[j], a, __float_as_uint(bv.x), __float_as_uint(bv.y));
            }
        }
        __syncthreads();   // all K/V/P reads done before next fill
    }

    // ---- epilogue ----
    float inv0 = 1.0f / l0, inv1 = 1.0f / l1;
    int q0 = qb * 128 + warp * 16 + g;
    float* o0 = g_attn + (size_t)b * SEQ * D_MODEL + (size_t)q0 * D_MODEL + h * HDIM;
    float* o1 = o0 + 8 * D_MODEL;
    #pragma unroll
    for (int j = 0; j < 8; ++j) {
        int c = j * 8 + 2 * t;
        *(float2*)(o0 + c) = make_float2(of[j][0] * inv0, of[j][1] * inv0);
        *(float2*)(o1 + c) = make_float2(of[j][2] * inv1, of[j][3] * inv1);
    }
}

// ===========================================================================
// Projection: out = g_attn @ W^T + b.  Block tile 128x256, 512 thr, 16 warps.
// Warp (wr=warp>>2, wc=warp&3): 32x64 tile.  K-chunk 32, double-buffered.
// ===========================================================================
#define PJ_AF 4096    // kg4 x mblk8 x 128
#define PJ_BF 8192    // kg4 x nblk32 x 64

__global__ void __launch_bounds__(512)
proj_kernel(const float* __restrict__ W,
            const float* __restrict__ bias,
            float* __restrict__ out) {
    extern __shared__ float sm[];
    // [buf][A(4096) then B(8192)]
    const int nb = blockIdx.x, mb = blockIdx.y;
    const int tid  = threadIdx.x;
    const int lane = tid & 31, warp = tid >> 5;
    const int g    = lane >> 2, t = lane & 3;
    const int wr   = warp >> 2, wc = warp & 3;

    const float* Ab = g_attn + (size_t)mb * 128 * D_MODEL;
    const float* Bb = W + (size_t)nb * 256 * D_MODEL;

    float acc[2][8][4];
    #pragma unroll
    for (int i = 0; i < 2; ++i)
        #pragma unroll
        for (int j = 0; j < 8; ++j)
            #pragma unroll
            for (int q = 0; q < 4; ++q) acc[i][j][q] = 0.0f;

    float4 stA[2], stB[4];

    // stage loader: A 128x32 (1024 f4), B 256x32 (2048 f4)
    auto ldg_stage = [&](int kb) {
        #pragma unroll
        for (int p = 0; p < 2; ++p) {
            int i = tid + p * 512;
            stA[p] = *(const float4*)(Ab + (size_t)(i >> 3) * D_MODEL
                                      + kb * 32 + (i & 7) * 4);
        }
        #pragma unroll
        for (int p = 0; p < 4; ++p) {
            int i = tid + p * 512;
            stB[p] = *(const float4*)(Bb + (size_t)(i >> 3) * D_MODEL
                                      + kb * 32 + (i & 7) * 4);
        }
    };
    auto sts_stage = [&](int buf) {
        float* As2 = sm + buf * (PJ_AF + PJ_BF);
        float* Ws2 = As2 + PJ_AF;
        #pragma unroll
        for (int p = 0; p < 2; ++p) {
            int i = tid + p * 512;
            int m = i >> 3, kq = i & 7;
            float va[4] = {tf32r(stA[p].x), tf32r(stA[p].y),
                           tf32r(stA[p].z), tf32r(stA[p].w)};
            int mblk = m >> 4, r = m & 15, him = r >> 3, gg = r & 7;
            int kg = kq >> 1, slot = him + 2 * (kq & 1);
            #pragma unroll
            for (int s = 0; s < 4; ++s) {
                int e = (s + gg + kg) & 3;
                As2[paA(kg, mblk, gg * 4 + e, 8) + slot] = va[e];
            }
        }
        #pragma unroll
        for (int p = 0; p < 4; ++p) {
            int i = tid + p * 512;
            int n = i >> 3, kq = i & 7;
            float va[4] = {tf32r(stB[p].x), tf32r(stB[p].y),
                           tf32r(stB[p].z), tf32r(stB[p].w)};
            int nblk = n >> 3, gg = n & 7;
            int kg = kq >> 1, pp = kq & 1;
            #pragma unroll
            for (int s = 0; s < 4; ++s) {
                int e = (s + kg) & 3;
                Ws2[paB(kg, nblk, gg * 4 + e, 32) + pp] = va[e];
            }
        }
    };

    ldg_stage(0);
    sts_stage(0);
    __syncthreads();

    for (int kb = 0; kb < D_MODEL / 32; ++kb) {
        if (kb + 1 < D_MODEL / 32) ldg_stage(kb + 1);

        const float* As2 = sm + (kb & 1) * (PJ_AF + PJ_BF);
        const float* Ws2 = As2 + PJ_AF;
        #pragma unroll
        for (int kg = 0; kg < 4; ++kg) {
            float4 a0 = *(const float4*)(As2 + paA(kg, 2 * wr,     lane, 8));
            float4 a1 = *(const float4*)(As2 + paA(kg, 2 * wr + 1, lane, 8));
            #pragma unroll
            for (int j = 0; j < 8; ++j) {
                float2 bv = *(const float2*)(Ws2 + paB(kg, wc * 8 + j, lane, 32));
                uint32_t b0 = __float_as_uint(bv.x), b1 = __float_as_uint(bv.y);
                mma8(acc[0][j], a0, b0, b1);
                mma8(acc[1][j], a1, b0, b1);
            }
        }

        if (kb + 1 < D_MODEL / 32) sts_stage((kb + 1) & 1);
        __syncthreads();
    }

    // epilogue
    #pragma unroll
    for (int i16 = 0; i16 < 2; ++i16) {
        int mr0 = mb * 128 + wr * 32 + i16 * 16 + g;
        float* r0 = out + (size_t)mr0 * D_MODEL + nb * 256 + wc * 64;
        float* r1 = r0 + 8 * D_MODEL;
        #pragma unroll
        for (int j = 0; j < 8; ++j) {
            int c = j * 8 + 2 * t;
            float bv0 = bias[nb * 256 + wc * 64 + c];
            float bv1 = bias[nb * 256 + wc * 64 + c + 1];
            *(float2*)(r0 + c) = make_float2(acc[i16][j][0] + bv0,
                                             acc[i16][j][1] + bv1);
            *(float2*)(r1 + c) = make_float2(acc[i16][j][2] + bv0,
                                             acc[i16][j][3] + bv1);
        }
    }
}

// ===========================================================================
extern "C" void kernel_launch(void* const* d_in, const int* in_sizes, int n_in,
                              void* d_out, int out_size) {
    const float* Q   = (const float*)d_in[0];
    const float* K   = (const float*)d_in[1];
    const float* V   = (const float*)d_in[2];
    const float* W_H = (const float*)d_in[3];
    const float* b_H = (const float*)d_in[4];
    (void)in_sizes; (void)n_in; (void)out_size;

    const int attn_smem = (AT_QF + AT_KF + AT_VF + AT_PF) * sizeof(float); // 96KB
    cudaFuncSetAttribute(attn_kernel,
                         cudaFuncAttributeMaxDynamicSharedMemorySize, attn_smem);
    dim3 agrid(SEQ / 128, HEADS, BATCH);
    attn_kernel<<<agrid, 256, attn_smem>>>(Q, K, V);

    const int proj_smem = 2 * (PJ_AF + PJ_BF) * sizeof(float);             // 96KB
    cudaFuncSetAttribute(proj_kernel,
                         cudaFuncAttributeMaxDynamicSharedMemorySize, proj_smem);
    dim3 pgrid(D_MODEL / 256, (BATCH * SEQ) / 128);
    proj_kernel<<<pgrid, 512, proj_smem>>>(W_H, b_H, (float*)d_out);
}

// round 6
// speedup vs baseline: 3.7047x; 1.4648x over previous
#include <cuda_runtime.h>
#include <math.h>
#include <cstdint>

#define D_MODEL 1024
#define HEADS   16
#define HDIM    64
#define BATCH   4
#define SEQ     1024
#define SCALE   0.03125f   // 1/sqrt(1024)

// Scratch for attention output [B, L, D]
__device__ float g_attn[BATCH * SEQ * D_MODEL];

// ---------------------------------------------------------------------------
// PTX helpers
// ---------------------------------------------------------------------------
__device__ __forceinline__ float tf32r(float x) {
    uint32_t u;
    asm("cvt.rna.tf32.f32 %0, %1;" : "=r"(u) : "f"(x));
    return __uint_as_float(u);
}
__device__ __forceinline__ uint32_t smem_u32(const void* p) {
    uint32_t a;
    asm("{ .reg .u64 t; cvta.to.shared.u64 t, %1; cvt.u32.u64 %0, t; }"
        : "=r"(a) : "l"(p));
    return a;
}
#define CP_ASYNC16(dst, src) \
    asm volatile("cp.async.cg.shared.global [%0], [%1], 16;" \
                 :: "r"(dst), "l"(src) : "memory")
#define CP_COMMIT() asm volatile("cp.async.commit_group;" ::: "memory")
#define CP_WAIT(n)  asm volatile("cp.async.wait_group %0;" :: "n"(n) : "memory")

// mma.sync m16n8k8 tf32:
// A frag: a.x=(g,t) a.y=(g+8,t) a.z=(g,t+4) a.w=(g+8,t+4);  g=lane>>2, t=lane&3
// B frag: b0=(k=t,n=g) b1=(k=t+4,n=g)
// C frag: c0=(g,2t) c1=(g,2t+1) c2=(g+8,2t) c3=(g+8,2t+1)
__device__ __forceinline__ void mma8(float c[4], const float4& a,
                                     uint32_t b0, uint32_t b1) {
    asm volatile(
        "mma.sync.aligned.m16n8k8.row.col.f32.tf32.tf32.f32 "
        "{%0,%1,%2,%3}, {%4,%5,%6,%7}, {%8,%9}, {%0,%1,%2,%3};"
        : "+f"(c[0]), "+f"(c[1]), "+f"(c[2]), "+f"(c[3])
        : "r"(__float_as_uint(a.x)), "r"(__float_as_uint(a.y)),
          "r"(__float_as_uint(a.z)), "r"(__float_as_uint(a.w)),
          "r"(b0), "r"(b1));
}
#define FB(x) __float_as_uint(x)

// ===========================================================================
// Flash attention.  Block = (q-tile 128, head, batch), 256 thr, 8 warps.
// Q in registers (warp-private, loaded once).  K/V in cp.async double-buffered
// smem tiles [64 rows][64 floats], 16B-swizzled: unit16(row,col4) =
// row*16 + (col4 ^ (row&15)).  P stays in registers (shfl C->A transform).
// ===========================================================================
__global__ void __launch_bounds__(256, 2)
attn_kernel(const float* __restrict__ Q,
            const float* __restrict__ K,
            const float* __restrict__ V) {
    extern __shared__ float sm[];   // [2 bufs][K 4096 | V 4096] floats = 64KB
    const uint32_t smb = smem_u32(sm);

    const int qb = blockIdx.x, h = blockIdx.y, b = blockIdx.z;
    const int tid  = threadIdx.x;
    const int lane = tid & 31, warp = tid >> 5;
    const int g    = lane >> 2, t = lane & 3;

    const size_t base = (size_t)b * SEQ * D_MODEL + (size_t)h * HDIM;
    const float* Qb = Q + base;
    const float* Kb = K + base;
    const float* Vb = V + base;

    // ---- Q fragments in registers (scaled + rna-rounded) ----
    float4 qa[8];
    {
        const float* q0 = Qb + (size_t)(qb * 128 + warp * 16 + g) * D_MODEL;
        const float* q1 = q0 + 8 * D_MODEL;
        #pragma unroll
        for (int kg = 0; kg < 8; ++kg) {
            qa[kg].x = tf32r(q0[kg * 8 + t] * SCALE);
            qa[kg].y = tf32r(q1[kg * 8 + t] * SCALE);
            qa[kg].z = tf32r(q0[kg * 8 + t + 4] * SCALE);
            qa[kg].w = tf32r(q1[kg * 8 + t + 4] * SCALE);
        }
    }

    // ---- async K/V tile fill (raw fp32; HMMA truncates to tf32) ----
    const int fcol4 = tid & 15;         // constant per thread
    const int frow0 = tid >> 4;
    auto fill = [&](int kb, int buf) {
        uint32_t kdst = smb + buf * 8192 * 4;
        uint32_t vdst = kdst + 4096 * 4;
        const float* ks = Kb + (size_t)(kb * 64) * D_MODEL + fcol4 * 4;
        const float* vs = Vb + (size_t)(kb * 64) * D_MODEL + fcol4 * 4;
        #pragma unroll
        for (int p = 0; p < 4; ++p) {
            int row = frow0 + p * 16;
            uint32_t u16 = (uint32_t)(row * 16 + (fcol4 ^ (row & 15)));
            CP_ASYNC16(kdst + u16 * 16, ks + (size_t)row * D_MODEL);
            CP_ASYNC16(vdst + u16 * 16, vs + (size_t)row * D_MODEL);
        }
    };

    float of[8][4];
    #pragma unroll
    for (int j = 0; j < 8; ++j)
        #pragma unroll
        for (int i = 0; i < 4; ++i) of[j][i] = 0.0f;
    float m0 = -INFINITY, m1 = -INFINITY, l0 = 0.0f, l1 = 0.0f;

    fill(0, 0); CP_COMMIT();

    for (int kb = 0; kb < SEQ / 64; ++kb) {
        if (kb + 1 < SEQ / 64) { fill(kb + 1, (kb + 1) & 1); CP_COMMIT(); CP_WAIT(1); }
        else                   { CP_WAIT(0); }
        __syncthreads();                     // tile kb visible to all warps

        const float* Ksm = sm + (kb & 1) * 8192;
        const float* Vsm = Ksm + 4096;

        // ---- S = Q @ K^T  (warp tile 16x64) ----
        // b0 = K[row=8j+g][d=kg*8+t] at row*64 + ((kg*2)^(row&15))*4 + t
        float sf[8][4];
        #pragma unroll
        for (int j = 0; j < 8; ++j)
            #pragma unroll
            for (int i = 0; i < 4; ++i) sf[j][i] = 0.0f;

        #pragma unroll
        for (int j = 0; j < 8; ++j) {
            int row = j * 8 + g;
            int x   = row & 15;
            const float* kr = Ksm + row * 64 + t;
            #pragma unroll
            for (int kg = 0; kg < 8; ++kg) {
                float b0 = kr[((kg * 2)     ^ x) * 4];
                float b1 = kr[((kg * 2 + 1) ^ x) * 4];
                mma8(sf[j], qa[kg], FB(b0), FB(b1));
            }
        }

        // ---- online softmax ----
        float rm0 = -INFINITY, rm1 = -INFINITY;
        #pragma unroll
        for (int j = 0; j < 8; ++j) {
            rm0 = fmaxf(rm0, fmaxf(sf[j][0], sf[j][1]));
            rm1 = fmaxf(rm1, fmaxf(sf[j][2], sf[j][3]));
        }
        rm0 = fmaxf(rm0, __shfl_xor_sync(0xffffffffu, rm0, 1));
        rm0 = fmaxf(rm0, __shfl_xor_sync(0xffffffffu, rm0, 2));
        rm1 = fmaxf(rm1, __shfl_xor_sync(0xffffffffu, rm1, 1));
        rm1 = fmaxf(rm1, __shfl_xor_sync(0xffffffffu, rm1, 2));
        float mn0 = fmaxf(m0, rm0), mn1 = fmaxf(m1, rm1);
        float al0 = __expf(m0 - mn0), al1 = __expf(m1 - mn1);
        m0 = mn0; m1 = mn1;
        float rs0 = 0.0f, rs1 = 0.0f;
        #pragma unroll
        for (int j = 0; j < 8; ++j) {
            sf[j][0] = __expf(sf[j][0] - mn0);
            sf[j][1] = __expf(sf[j][1] - mn0);
            sf[j][2] = __expf(sf[j][2] - mn1);
            sf[j][3] = __expf(sf[j][3] - mn1);
            rs0 += sf[j][0] + sf[j][1];
            rs1 += sf[j][2] + sf[j][3];
        }
        rs0 += __shfl_xor_sync(0xffffffffu, rs0, 1);
        rs0 += __shfl_xor_sync(0xffffffffu, rs0, 2);
        rs1 += __shfl_xor_sync(0xffffffffu, rs1, 1);
        rs1 += __shfl_xor_sync(0xffffffffu, rs1, 2);
        l0 = l0 * al0 + rs0;
        l1 = l1 * al1 + rs1;
        #pragma unroll
        for (int j = 0; j < 8; ++j) {
            of[j][0] *= al0; of[j][1] *= al0;
            of[j][2] *= al1; of[j][3] *= al1;
        }

        // ---- O += P @ V, P converted C-frag -> A-frag in registers ----
        // col t held by lane (g, t>>1), parity t&1; col t+4 by lane (g, (t>>1)+2)
        const int src1 = (lane & ~3) | (t >> 1);
        const int src2 = src1 + 2;
        const bool odd = (t & 1);
        #pragma unroll
        for (int jk = 0; jk < 8; ++jk) {
            float ev, od, a0, a1, a2, a3;
            ev = __shfl_sync(0xffffffffu, sf[jk][0], src1);
            od = __shfl_sync(0xffffffffu, sf[jk][1], src1);
            a0 = odd ? od : ev;
            ev = __shfl_sync(0xffffffffu, sf[jk][2], src1);
            od = __shfl_sync(0xffffffffu, sf[jk][3], src1);
            a1 = odd ? od : ev;
            ev = __shfl_sync(0xffffffffu, sf[jk][0], src2);
            od = __shfl_sync(0xffffffffu, sf[jk][1], src2);
            a2 = odd ? od : ev;
            ev = __shfl_sync(0xffffffffu, sf[jk][2], src2);
            od = __shfl_sync(0xffffffffu, sf[jk][3], src2);
            a3 = odd ? od : ev;
            float4 pa = make_float4(tf32r(a0), tf32r(a1), tf32r(a2), tf32r(a3));

            // b0 = V[kv=jk*8+t][d=jj*8+g]
            int r0 = jk * 8 + t, r1 = r0 + 4;
            const float* v0 = Vsm + r0 * 64;
            const float* v1 = Vsm + r1 * 64;
            int x0 = r0 & 15, x1 = r1 & 15;
            #pragma unroll
            for (int jj = 0; jj < 8; ++jj) {
                int col = jj * 8 + g;
                int c4 = col >> 2, e = col & 3;
                float b0 = v0[(c4 ^ x0) * 4 + e];
                float b1 = v1[(c4 ^ x1) * 4 + e];
                mma8(of[jj], pa, FB(b0), FB(b1));
            }
        }
        __syncthreads();   // all reads of buf kb&1 done before iter kb+1 refills it
    }

    // ---- epilogue ----
    float inv0 = 1.0f / l0, inv1 = 1.0f / l1;
    int q0 = qb * 128 + warp * 16 + g;
    float* o0 = g_attn + (size_t)b * SEQ * D_MODEL + (size_t)q0 * D_MODEL + h * HDIM;
    float* o1 = o0 + 8 * D_MODEL;
    #pragma unroll
    for (int j = 0; j < 8; ++j) {
        int c = j * 8 + 2 * t;
        *(float2*)(o0 + c) = make_float2(of[j][0] * inv0, of[j][1] * inv0);
        *(float2*)(o1 + c) = make_float2(of[j][2] * inv1, of[j][3] * inv1);
    }
}

// ===========================================================================
// Projection: out = g_attn @ W^T + b.  Block 128x256, 512 thr, 16 warps
// (warp tile 32x64).  K-chunk 32, cp.async double-buffered.
// Tile layout [rows][32 floats], unit16(row,col4) = row*8 + (col4 ^ (row&7)).
// ===========================================================================
#define PJ_TILE (128 * 32 + 256 * 32)   // floats per buffer = 12288

__global__ void __launch_bounds__(512, 1)
proj_kernel(const float* __restrict__ W,
            const float* __restrict__ bias,
            float* __restrict__ out) {
    extern __shared__ float sm[];       // 2 * 12288 floats = 96KB
    const uint32_t smb = smem_u32(sm);

    const int nb = blockIdx.x, mb = blockIdx.y;
    const int tid  = threadIdx.x;
    const int lane = tid & 31, warp = tid >> 5;
    const int g    = lane >> 2, t = lane & 3;
    const int wr   = warp >> 2, wc = warp & 3;

    const float* Ab = g_attn + (size_t)mb * 128 * D_MODEL;
    const float* Bb = W + (size_t)nb * 256 * D_MODEL;

    const int fcol4 = tid & 7;          // constant per thread
    const int farow = tid >> 3;         // A row base (0..63), +64 for p=1
    auto fill = [&](int kb, int buf) {
        uint32_t adst = smb + buf * PJ_TILE * 4;
        uint32_t bdst = adst + 128 * 32 * 4;
        const float* as = Ab + (size_t)kb * 32 + fcol4 * 4;
        const float* bs = Bb + (size_t)kb * 32 + fcol4 * 4;
        #pragma unroll
        for (int p = 0; p < 2; ++p) {
            int row = farow + p * 64;
            uint32_t u16 = (uint32_t)(row * 8 + (fcol4 ^ (row & 7)));
            CP_ASYNC16(adst + u16 * 16, as + (size_t)row * D_MODEL);
        }
        #pragma unroll
        for (int p = 0; p < 4; ++p) {
            int row = farow + p * 64;
            uint32_t u16 = (uint32_t)(row * 8 + (fcol4 ^ (row & 7)));
            CP_ASYNC16(bdst + u16 * 16, bs + (size_t)row * D_MODEL);
        }
    };

    float acc[2][8][4];
    #pragma unroll
    for (int i = 0; i < 2; ++i)
        #pragma unroll
        for (int j = 0; j < 8; ++j)
            #pragma unroll
            for (int q = 0; q < 4; ++q) acc[i][j][q] = 0.0f;

    fill(0, 0); CP_COMMIT();

    for (int kb = 0; kb < D_MODEL / 32; ++kb) {
        if (kb + 1 < D_MODEL / 32) { fill(kb + 1, (kb + 1) & 1); CP_COMMIT(); CP_WAIT(1); }
        else                       { CP_WAIT(0); }
        __syncthreads();

        const float* As = sm + (kb & 1) * PJ_TILE;
        const float* Bs = As + 128 * 32;

        #pragma unroll
        for (int kg = 0; kg < 4; ++kg) {
            float4 af[2];
            #pragma unroll
            for (int i16 = 0; i16 < 2; ++i16) {
                int r0 = wr * 32 + i16 * 16 + g;
                int r1 = r0 + 8;
                const float* a0p = As + r0 * 32 + t;
                const float* a1p = As + r1 * 32 + t;
                int x0 = r0 & 7, x1 = r1 & 7;
                af[i16].x = a0p[((kg * 2)     ^ x0) * 4];
                af[i16].y = a1p[((kg * 2)     ^ x1) * 4];
                af[i16].z = a0p[((kg * 2 + 1) ^ x0) * 4];
                af[i16].w = a1p[((kg * 2 + 1) ^ x1) * 4];
            }
            #pragma unroll
            for (int j = 0; j < 8; ++j) {
                int n = wc * 64 + j * 8 + g;
                const float* bp = Bs + n * 32 + t;
                int x = n & 7;
                float b0 = bp[((kg * 2)     ^ x) * 4];
                float b1 = bp[((kg * 2 + 1) ^ x) * 4];
                mma8(acc[0][j], af[0], FB(b0), FB(b1));
                mma8(acc[1][j], af[1], FB(b0), FB(b1));
            }
        }
        __syncthreads();
    }

    // epilogue
    #pragma unroll
    for (int i16 = 0; i16 < 2; ++i16) {
        int mr0 = mb * 128 + wr * 32 + i16 * 16 + g;
        float* r0 = out + (size_t)mr0 * D_MODEL + nb * 256 + wc * 64;
        float* r1 = r0 + 8 * D_MODEL;
        #pragma unroll
        for (int j = 0; j < 8; ++j) {
            int c = j * 8 + 2 * t;
            float bv0 = bias[nb * 256 + wc * 64 + c];
            float bv1 = bias[nb * 256 + wc * 64 + c + 1];
            *(float2*)(r0 + c) = make_float2(acc[i16][j][0] + bv0,
                                             acc[i16][j][1] + bv1);
            *(float2*)(r1 + c) = make_float2(acc[i16][j][2] + bv0,
                                             acc[i16][j][3] + bv1);
        }
    }
}

// ===========================================================================
extern "C" void kernel_launch(void* const* d_in, const int* in_sizes, int n_in,
                              void* d_out, int out_size) {
    const float* Q   = (const float*)d_in[0];
    const float* K   = (const float*)d_in[1];
    const float* V   = (const float*)d_in[2];
    const float* W_H = (const float*)d_in[3];
    const float* b_H = (const float*)d_in[4];
    (void)in_sizes; (void)n_in; (void)out_size;

    const int attn_smem = 2 * 8192 * sizeof(float);   // 64KB
    cudaFuncSetAttribute(attn_kernel,
                         cudaFuncAttributeMaxDynamicSharedMemorySize, attn_smem);
    dim3 agrid(SEQ / 128, HEADS, BATCH);
    attn_kernel<<<agrid, 256, attn_smem>>>(Q, K, V);

    const int proj_smem = 2 * PJ_TILE * sizeof(float); // 96KB
    cudaFuncSetAttribute(proj_kernel,
                         cudaFuncAttributeMaxDynamicSharedMemorySize, proj_smem);
    dim3 pgrid(D_MODEL / 256, (BATCH * SEQ) / 128);
    proj_kernel<<<pgrid, 512, proj_smem>>>(W_H, b_H, (float*)d_out);
}